// round 12
// baseline (speedup 1.0000x reference)
#include <cuda_runtime.h>
#include <cstdint>

#define BB 256
#define TT 1024
#define HH 128
#define II 19
#define STG_T 16       // timesteps per cp.async stage
#define WSTRIDE 132    // W_ih1 smem row stride in floats (conflict-free LDS.128)
#define WSH_BYTES (HH * WSTRIDE * 4)

// Scratch (device globals; no runtime allocation allowed)
__device__ float g_pre1[BB * TT * HH];  // layer-0 pre-activations (proj0 out)
__device__ float g_pre2[BB * TT * HH];  // layer-1 pre-activations (fused out)

typedef unsigned long long ull;

__device__ __forceinline__ ull ffma2(ull a, ull b, ull c) {
    ull d;
    asm("fma.rn.f32x2 %0, %1, %2, %3;" : "=l"(d) : "l"(a), "l"(b), "l"(c));
    return d;
}

__device__ __forceinline__ ull fadd2(ull a, ull b) {
    ull d;
    asm("add.rn.f32x2 %0, %1, %2;" : "=l"(d) : "l"(a), "l"(b));
    return d;
}

__device__ __forceinline__ float hsum2(ull a) {
    float x, y;
    asm("mov.b64 {%0, %1}, %2;" : "=f"(x), "=f"(y) : "l"(a));
    return x + y;
}

// single-MUFU tanh (validated R10: final rel_err 5.5e-6)
__device__ __forceinline__ float fast_tanh(float x) {
    float r;
    asm("tanh.approx.f32 %0, %1;" : "=f"(r) : "f"(x));
    return r;
}

__device__ __forceinline__ uint32_t s2u(const void* p) {
    return (uint32_t)__cvta_generic_to_shared(p);
}
#define CP_ASYNC16(dst, src) \
    asm volatile("cp.async.ca.shared.global [%0], [%1], 16;" :: "r"(dst), "l"(src))
#define CP_COMMIT() asm volatile("cp.async.commit_group;" ::: "memory")
#define CP_WAIT0()  asm volatile("cp.async.wait_group 0;" ::: "memory")
#define CP_WAIT1()  asm volatile("cp.async.wait_group 1;" ::: "memory")

// ---------------------------------------------------------------------------
// proj0: pre1 = x @ W_ih0^T + (b_ih0 + b_hh0).  x:[B,T,19], W:[128,19]
// ---------------------------------------------------------------------------
#define ROWS0 8
__global__ void __launch_bounds__(128) proj0_kernel(
    const float* __restrict__ x,
    const float* __restrict__ Wih,
    const float* __restrict__ bih,
    const float* __restrict__ bhh)
{
    __shared__ float xs[ROWS0 * II];
    const int j   = threadIdx.x;
    const int blk = blockIdx.x;

    float w[II];
#pragma unroll
    for (int i = 0; i < II; i++) w[i] = Wih[j * II + i];
    const float bias = bih[j] + bhh[j];

    const float* src = x + (size_t)blk * ROWS0 * II;
    for (int i = j; i < ROWS0 * II; i += 128) xs[i] = src[i];
    __syncthreads();

#pragma unroll
    for (int r = 0; r < ROWS0; r++) {
        float acc = bias;
#pragma unroll
        for (int i = 0; i < II; i++) acc += xs[r * II + i] * w[i];
        g_pre1[((size_t)blk * ROWS0 + r) * HH + j] = acc;
    }
}

// ---------------------------------------------------------------------------
// common: cp.async staging of one 16-step stage of pre (one row), 128 threads
// ---------------------------------------------------------------------------
__device__ __forceinline__ void stage_prefetch(float* dst, const float* pre,
                                               int t0, int j) {
    uint32_t dbase = s2u(dst);
#pragma unroll
    for (int it = 0; it < 4; it++) {
        int lin = it * 128 + j;                 // [0,512) 16B chunks
        int tt  = lin >> 5;                     // timestep within stage
        int c   = lin & 31;                     // 16B chunk within row
        CP_ASYNC16(dbase + lin * 16, pre + (size_t)(t0 + tt) * HH + c * 4);
    }
}

// ---------------------------------------------------------------------------
// fused1: layer-0 scan + layer-1 input projection (dead-end branch).
// Iteration i:  h1_i = tanh(pre1_i + W_hh0 h1_{i-1})        [serial chain]
//               pre2_{i-1} = b2 + W_ih1 h1_{i-1}            [off-chain]
// Both dots share the same 16 broadcast LDS.128 of h1_{i-1}. One row per CTA,
// 256 CTAs, 2 CTAs/SM (2 independent barrier groups per SMSP). W_hh0 row in
// 64 packed regs; W_ih1 row in dynamic smem (stride 132 -> conflict-free
// private LDS.128). pre1 staged via cp.async double-buffered stages.
// ---------------------------------------------------------------------------
__global__ void __launch_bounds__(128, 2) fused1_kernel(
    const float* __restrict__ Whh0,
    const float* __restrict__ Wih1,
    const float* __restrict__ bih1,
    const float* __restrict__ bhh1)
{
    extern __shared__ __align__(16) float wsh[];         // [HH][WSTRIDE]
    __shared__ __align__(16) float hs[2][HH];            // double-buffered h1
    __shared__ __align__(16) float ps[2][STG_T * HH];    // staged pre1
    const int j = threadIdx.x;
    const int b = blockIdx.x;

    const float* pre = g_pre1 + (size_t)b * TT * HH;

    // stages 0,1 in flight before the long-latency W loads
    stage_prefetch(ps[0], pre, 0, j);
    CP_COMMIT();
    stage_prefetch(ps[1], pre, STG_T, j);
    CP_COMMIT();

    // W_ih1 -> smem, row stride WSTRIDE (conflict-free per 8-lane phase)
    {
        const float4* src = (const float4*)Wih1;
        for (int i = j; i < HH * HH / 4; i += 128) {
            int r  = i / (HH / 4);
            int c4 = i % (HH / 4);
            *(float4*)&wsh[r * WSTRIDE + c4 * 4] = src[i];
        }
    }

    // W_hh0 row j -> 64 packed regs
    ull w[64];
    {
        const ulonglong2* wr = (const ulonglong2*)(Whh0 + j * HH);
#pragma unroll
        for (int q = 0; q < 32; q++) {
            ulonglong2 t = wr[q];
            w[2 * q]     = t.x;
            w[2 * q + 1] = t.y;
        }
    }
    const float b2 = bih1[j] + bhh1[j];
    const ulonglong2* wih = (const ulonglong2*)(wsh + j * WSTRIDE);

    float* prow2 = g_pre2 + (size_t)b * TT * HH + j;

    hs[0][j] = 0.0f;
    __syncthreads();    // also covers wsh visibility

    const int nst = TT / STG_T;
#pragma unroll 1
    for (int s = 0; s < nst; s++) {
        const int buf = s & 1;
        if (s + 1 < nst) { CP_WAIT1(); } else { CP_WAIT0(); }
        __syncthreads();

        const float* pst = ps[buf];
        const int tbase = s * STG_T;
#pragma unroll 1
        for (int tl = 0; tl < STG_T; tl++) {
            const int ii = tbase + tl;
            const int rb = ii & 1;               // read buffer
            const float* hp = hs[rb];
            float p = pst[tl * HH + j];

            const ulonglong2* h2 = (const ulonglong2*)hp;
            ull a0 = 0, a1 = 0, a2 = 0, a3 = 0, a4 = 0, a5 = 0, a6 = 0, a7 = 0;
            ull c0 = 0, c1 = 0, c2 = 0, c3 = 0;
#pragma unroll
            for (int q = 0; q < 8; q++) {
                ulonglong2 v0 = h2[4 * q];
                ulonglong2 v1 = h2[4 * q + 1];
                ulonglong2 v2 = h2[4 * q + 2];
                ulonglong2 v3 = h2[4 * q + 3];
                ulonglong2 u0 = wih[4 * q];
                ulonglong2 u1 = wih[4 * q + 1];
                ulonglong2 u2 = wih[4 * q + 2];
                ulonglong2 u3 = wih[4 * q + 3];
                // serial-chain dot (W_hh0), 8 chains
                a0 = ffma2(v0.x, w[8 * q],     a0);
                a1 = ffma2(v0.y, w[8 * q + 1], a1);
                a2 = ffma2(v1.x, w[8 * q + 2], a2);
                a3 = ffma2(v1.y, w[8 * q + 3], a3);
                a4 = ffma2(v2.x, w[8 * q + 4], a4);
                a5 = ffma2(v2.y, w[8 * q + 5], a5);
                a6 = ffma2(v3.x, w[8 * q + 6], a6);
                a7 = ffma2(v3.y, w[8 * q + 7], a7);
                // dead-end dot (W_ih1), 4 chains, reuses v0..v3
                c0 = ffma2(v0.x, u0.x, c0);
                c1 = ffma2(v0.y, u0.y, c1);
                c2 = ffma2(v1.x, u1.x, c2);
                c3 = ffma2(v1.y, u1.y, c3);
                c0 = ffma2(v2.x, u2.x, c0);
                c1 = ffma2(v2.y, u2.y, c1);
                c2 = ffma2(v3.x, u3.x, c2);
                c3 = ffma2(v3.y, u3.y, c3);
            }
            ull sa = fadd2(fadd2(fadd2(a0, a1), fadd2(a2, a3)),
                           fadd2(fadd2(a4, a5), fadd2(a6, a7)));
            float hn = fast_tanh(p + hsum2(sa));

            ull sc = fadd2(fadd2(c0, c1), fadd2(c2, c3));
            float p2 = b2 + hsum2(sc);

            hs[rb ^ 1][j] = hn;
            if (ii > 0) prow2[(size_t)(ii - 1) * HH] = p2;
            __syncthreads();
        }

        // refill stage s+2 into the buffer just consumed
        if (s + 2 < nst) {
            stage_prefetch(ps[buf], pre, (s + 2) * STG_T, j);
        }
        CP_COMMIT();
    }

    // epilogue: pre2_{1023} from h1_{1023} (in hs[0]; t=1023 odd wrote hs[0])
    {
        const ulonglong2* h2 = (const ulonglong2*)hs[0];
        ull c0 = 0, c1 = 0, c2 = 0, c3 = 0;
#pragma unroll
        for (int q = 0; q < 8; q++) {
            ulonglong2 v0 = h2[4 * q];
            ulonglong2 v1 = h2[4 * q + 1];
            ulonglong2 v2 = h2[4 * q + 2];
            ulonglong2 v3 = h2[4 * q + 3];
            ulonglong2 u0 = wih[4 * q];
            ulonglong2 u1 = wih[4 * q + 1];
            ulonglong2 u2 = wih[4 * q + 2];
            ulonglong2 u3 = wih[4 * q + 3];
            c0 = ffma2(v0.x, u0.x, c0);
            c1 = ffma2(v0.y, u0.y, c1);
            c2 = ffma2(v1.x, u1.x, c2);
            c3 = ffma2(v1.y, u1.y, c3);
            c0 = ffma2(v2.x, u2.x, c0);
            c1 = ffma2(v2.y, u2.y, c1);
            c2 = ffma2(v3.x, u3.x, c2);
            c3 = ffma2(v3.y, u3.y, c3);
        }
        ull sc = fadd2(fadd2(c0, c1), fadd2(c2, c3));
        prow2[(size_t)(TT - 1) * HH] = b2 + hsum2(sc);
    }
}

// ---------------------------------------------------------------------------
// scan2: h2_t = tanh(pre2_t + W_hh1 h2_{t-1}) -> out.  R10's proven scan.
// ---------------------------------------------------------------------------
__device__ __forceinline__ float scan_step1(const float* hp, const ull* w, float p) {
    const ulonglong2* h2 = (const ulonglong2*)hp;
    ull a0 = 0, a1 = 0, a2 = 0, a3 = 0, a4 = 0, a5 = 0, a6 = 0, a7 = 0;
#pragma unroll
    for (int q = 0; q < 8; q++) {
        ulonglong2 v0 = h2[4 * q];
        ulonglong2 v1 = h2[4 * q + 1];
        ulonglong2 v2 = h2[4 * q + 2];
        ulonglong2 v3 = h2[4 * q + 3];
        a0 = ffma2(v0.x, w[8 * q],     a0);
        a1 = ffma2(v0.y, w[8 * q + 1], a1);
        a2 = ffma2(v1.x, w[8 * q + 2], a2);
        a3 = ffma2(v1.y, w[8 * q + 3], a3);
        a4 = ffma2(v2.x, w[8 * q + 4], a4);
        a5 = ffma2(v2.y, w[8 * q + 5], a5);
        a6 = ffma2(v3.x, w[8 * q + 6], a6);
        a7 = ffma2(v3.y, w[8 * q + 7], a7);
    }
    ull s = fadd2(fadd2(fadd2(a0, a1), fadd2(a2, a3)),
                  fadd2(fadd2(a4, a5), fadd2(a6, a7)));
    return fast_tanh(p + hsum2(s));
}

__global__ void __launch_bounds__(128, 2) scan2_kernel(
    const float* __restrict__ Whh,
    float* __restrict__ outp)
{
    __shared__ __align__(16) float hs[2][HH];
    __shared__ __align__(16) float ps[2][STG_T * HH];
    const int j = threadIdx.x;
    const int b = blockIdx.x;

    const float* pre = g_pre2 + (size_t)b * TT * HH;

    stage_prefetch(ps[0], pre, 0, j);
    CP_COMMIT();
    stage_prefetch(ps[1], pre, STG_T, j);
    CP_COMMIT();

    ull w[64];
    {
        const ulonglong2* wr = (const ulonglong2*)(Whh + j * HH);
#pragma unroll
        for (int q = 0; q < 32; q++) {
            ulonglong2 t = wr[q];
            w[2 * q]     = t.x;
            w[2 * q + 1] = t.y;
        }
    }

    float* orow = outp + (size_t)b * TT * HH + j;

    hs[0][j] = 0.0f;
    __syncthreads();

    const int nst = TT / STG_T;
#pragma unroll 1
    for (int s = 0; s < nst; s++) {
        const int buf = s & 1;
        if (s + 1 < nst) { CP_WAIT1(); } else { CP_WAIT0(); }
        __syncthreads();

        const float* pst = ps[buf];
        const int tbase = s * STG_T;
#pragma unroll 1
        for (int tl = 0; tl < STG_T; tl += 2) {
            {
                float hn = scan_step1(hs[0], w, pst[tl * HH + j]);
                hs[1][j] = hn;
                orow[(size_t)(tbase + tl) * HH] = hn;
                __syncthreads();
            }
            {
                float hn = scan_step1(hs[1], w, pst[(tl + 1) * HH + j]);
                hs[0][j] = hn;
                orow[(size_t)(tbase + tl + 1) * HH] = hn;
                __syncthreads();
            }
        }

        if (s + 2 < nst) {
            stage_prefetch(ps[buf], pre, (s + 2) * STG_T, j);
        }
        CP_COMMIT();
    }
}

// ---------------------------------------------------------------------------
extern "C" void kernel_launch(void* const* d_in, const int* in_sizes, int n_in,
                              void* d_out, int out_size)
{
    const float* x     = (const float*)d_in[0];
    const float* Wih0  = (const float*)d_in[1];
    const float* Whh0  = (const float*)d_in[2];
    const float* bih0  = (const float*)d_in[3];
    const float* bhh0  = (const float*)d_in[4];
    const float* Wih1  = (const float*)d_in[5];
    const float* Whh1  = (const float*)d_in[6];
    const float* bih1  = (const float*)d_in[7];
    const float* bhh1  = (const float*)d_in[8];
    float* out = (float*)d_out;

    // opt-in dynamic smem for the fused kernel (idempotent, capture-safe)
    cudaFuncSetAttribute(fused1_kernel,
                         cudaFuncAttributeMaxDynamicSharedMemorySize, WSH_BYTES);

    proj0_kernel<<<BB * TT / ROWS0, 128>>>(x, Wih0, bih0, bhh0);
    fused1_kernel<<<BB, 128, WSH_BYTES>>>(Whh0, Wih1, bih1, bhh1);
    scan2_kernel<<<BB, 128>>>(Whh1, out);
}

// round 13
// speedup vs baseline: 1.2745x; 1.2745x over previous
#include <cuda_runtime.h>
#include <cstdint>

#define BB 256
#define TT 1024
#define HH 128
#define II 19
#define STG_T 32   // timesteps per cp.async stage in scan

// Scratch (device globals; no runtime allocation allowed)
__device__ float g_pre[BB * TT * HH];   // pre-activations for current layer
__device__ float g_out1[BB * TT * HH];  // layer-0 hidden outputs

typedef unsigned long long ull;

__device__ __forceinline__ ull ffma2(ull a, ull b, ull c) {
    ull d;
    asm("fma.rn.f32x2 %0, %1, %2, %3;" : "=l"(d) : "l"(a), "l"(b), "l"(c));
    return d;
}

__device__ __forceinline__ ull fadd2(ull a, ull b) {
    ull d;
    asm("add.rn.f32x2 %0, %1, %2;" : "=l"(d) : "l"(a), "l"(b));
    return d;
}

__device__ __forceinline__ float hsum2(ull a) {
    float x, y;
    asm("mov.b64 {%0, %1}, %2;" : "=f"(x), "=f"(y) : "l"(a));
    return x + y;
}

// single-MUFU tanh (validated R10: final rel_err 5.5e-6)
__device__ __forceinline__ float fast_tanh(float x) {
    float r;
    asm("tanh.approx.f32 %0, %1;" : "=f"(r) : "f"(x));
    return r;
}

__device__ __forceinline__ uint32_t s2u(const void* p) {
    return (uint32_t)__cvta_generic_to_shared(p);
}
#define CP_ASYNC16(dst, src) \
    asm volatile("cp.async.ca.shared.global [%0], [%1], 16;" :: "r"(dst), "l"(src))
#define CP_COMMIT() asm volatile("cp.async.commit_group;" ::: "memory")
#define CP_WAIT0()  asm volatile("cp.async.wait_group 0;" ::: "memory")
#define CP_WAIT1()  asm volatile("cp.async.wait_group 1;" ::: "memory")

// ---------------------------------------------------------------------------
// proj0: pre = x @ W_ih0^T + (b_ih0 + b_hh0).  x:[B,T,19], W:[128,19]
// ---------------------------------------------------------------------------
#define ROWS0 8
__global__ void __launch_bounds__(128) proj0_kernel(
    const float* __restrict__ x,
    const float* __restrict__ Wih,
    const float* __restrict__ bih,
    const float* __restrict__ bhh)
{
    __shared__ float xs[ROWS0 * II];
    const int j   = threadIdx.x;
    const int blk = blockIdx.x;

    float w[II];
#pragma unroll
    for (int i = 0; i < II; i++) w[i] = Wih[j * II + i];
    const float bias = bih[j] + bhh[j];

    const float* src = x + (size_t)blk * ROWS0 * II;
    for (int i = j; i < ROWS0 * II; i += 128) xs[i] = src[i];
    __syncthreads();

#pragma unroll
    for (int r = 0; r < ROWS0; r++) {
        float acc = bias;
#pragma unroll
        for (int i = 0; i < II; i++) acc += xs[r * II + i] * w[i];
        g_pre[((size_t)blk * ROWS0 + r) * HH + j] = acc;
    }
}

// ---------------------------------------------------------------------------
// proj1 (persistent): pre = out1 @ W_ih1^T + bias.  out1:[B*T,128], W:[128,128]
// 296 CTAs; W row per thread in 64 packed regs; 32-row tiles double-buffered
// via cp.async; INNER LOOP = 8 rows (32 packed acc chains) to halve the
// number of serial reduce/store tails per tile.
// ---------------------------------------------------------------------------
#define ROWS1 32
#define NT1   (BB * TT / ROWS1)
#define PJ1_GRID 296

__device__ __forceinline__ void pj1_prefetch(float* dst, int tile, int j) {
    uint32_t dbase = s2u(dst);
    const float* src = g_out1 + (size_t)tile * ROWS1 * HH;
#pragma unroll
    for (int it = 0; it < ROWS1 * HH / 4 / 128; it++) {   // 8 iters
        int lin = it * 128 + j;                 // [0,1024) 16B chunks
        CP_ASYNC16(dbase + lin * 16, src + lin * 4);
    }
}

__global__ void __launch_bounds__(128, 2) proj1_kernel(
    const float* __restrict__ Wih,
    const float* __restrict__ bih,
    const float* __restrict__ bhh)
{
    __shared__ __align__(16) float in_s[2][ROWS1 * HH];
    const int j = threadIdx.x;

    int t = blockIdx.x;
    if (t < NT1) pj1_prefetch(in_s[0], t, j);
    CP_COMMIT();

    ull w[64];
    {
        const ulonglong2* wr = (const ulonglong2*)(Wih + j * HH);
#pragma unroll
        for (int q = 0; q < 32; q++) {
            ulonglong2 tt = wr[q];
            w[2 * q]     = tt.x;
            w[2 * q + 1] = tt.y;
        }
    }
    const float bias = bih[j] + bhh[j];

    int buf = 0;
#pragma unroll 1
    while (t < NT1) {
        const int tn = t + PJ1_GRID;
        CP_WAIT0();
        __syncthreads();
        if (tn < NT1) { pj1_prefetch(in_s[buf ^ 1], tn, j); }
        CP_COMMIT();

        const float* ins = in_s[buf];
#pragma unroll 1
        for (int r = 0; r < ROWS1; r += 8) {
            // 8 rows, 4 packed chains each = 32 independent chains
            ull acc[8][4];
#pragma unroll
            for (int e = 0; e < 8; e++)
#pragma unroll
                for (int c = 0; c < 4; c++) acc[e][c] = 0;

#pragma unroll
            for (int q = 0; q < 16; q++) {
#pragma unroll
                for (int e = 0; e < 8; e++) {
                    const ulonglong2* hp =
                        (const ulonglong2*)(ins + (r + e) * HH);
                    ulonglong2 v0 = hp[2 * q];
                    ulonglong2 v1 = hp[2 * q + 1];
                    acc[e][0] = ffma2(v0.x, w[4 * q],     acc[e][0]);
                    acc[e][1] = ffma2(v0.y, w[4 * q + 1], acc[e][1]);
                    acc[e][2] = ffma2(v1.x, w[4 * q + 2], acc[e][2]);
                    acc[e][3] = ffma2(v1.y, w[4 * q + 3], acc[e][3]);
                }
            }
            size_t base = ((size_t)t * ROWS1 + r) * HH + j;
#pragma unroll
            for (int e = 0; e < 8; e++) {
                ull s = fadd2(fadd2(acc[e][0], acc[e][1]),
                              fadd2(acc[e][2], acc[e][3]));
                g_pre[base + (size_t)e * HH] = bias + hsum2(s);
            }
        }
        t = tn;
        buf ^= 1;
    }
}

// ---------------------------------------------------------------------------
// scan: h_t = tanh(pre_t + W_hh h_{t-1}).  ONE batch row per CTA, 256 CTAs,
// 2 CTAs/SM. W_hh row register-resident (64 packed regs), 4 accumulator
// chains (depth 16x4=64 cyc < 128-cyc issue window -> latency-safe, fewer
// reduce instrs). pre staged by cp.async in double-buffered 32-step stages.
// outp == nullptr -> write g_out1 (layer 0), else write outp (layer 1).
// ---------------------------------------------------------------------------
__device__ __forceinline__ void scan_prefetch(float* dst, const float* pre,
                                              int t0, int j) {
    uint32_t dbase = s2u(dst);
#pragma unroll
    for (int it = 0; it < STG_T * HH / 4 / 128; it++) {   // 8 iters
        int lin = it * 128 + j;                 // [0,1024) 16B chunks
        int tt  = lin >> 5;                     // timestep within stage
        int c   = lin & 31;                     // 16B chunk within row
        CP_ASYNC16(dbase + lin * 16, pre + (size_t)(t0 + tt) * HH + c * 4);
    }
}

__device__ __forceinline__ float scan_step1(const float* hp, const ull* w, float p) {
    const ulonglong2* h2 = (const ulonglong2*)hp;
    ull a0 = 0, a1 = 0, a2 = 0, a3 = 0;
#pragma unroll
    for (int q = 0; q < 16; q++) {
        ulonglong2 v = h2[2 * q];
        ulonglong2 u = h2[2 * q + 1];
        a0 = ffma2(v.x, w[4 * q],     a0);
        a1 = ffma2(v.y, w[4 * q + 1], a1);
        a2 = ffma2(u.x, w[4 * q + 2], a2);
        a3 = ffma2(u.y, w[4 * q + 3], a3);
    }
    ull s = fadd2(fadd2(a0, a1), fadd2(a2, a3));
    return fast_tanh(p + hsum2(s));
}

__global__ void __launch_bounds__(128, 2) scan_kernel(
    const float* __restrict__ Whh,
    float* __restrict__ outp)
{
    __shared__ __align__(16) float hs[2][HH];            // double-buffered h
    __shared__ __align__(16) float ps[2][STG_T * HH];    // staged pre
    const int j = threadIdx.x;
    const int b = blockIdx.x;

    const float* pre = g_pre + (size_t)b * TT * HH;

    // stages 0 and 1 in flight before the long-latency W load
    scan_prefetch(ps[0], pre, 0, j);
    CP_COMMIT();
    scan_prefetch(ps[1], pre, STG_T, j);
    CP_COMMIT();

    ull w[64];
    {
        const ulonglong2* wr = (const ulonglong2*)(Whh + j * HH);
#pragma unroll
        for (int q = 0; q < 32; q++) {
            ulonglong2 t = wr[q];
            w[2 * q]     = t.x;
            w[2 * q + 1] = t.y;
        }
    }

    float* out  = outp ? outp : g_out1;
    float* orow = out + (size_t)b * TT * HH + j;

    hs[0][j] = 0.0f;
    __syncthreads();

    const int nst = TT / STG_T;
#pragma unroll 1
    for (int s = 0; s < nst; s++) {
        const int buf = s & 1;
        if (s + 1 < nst) { CP_WAIT1(); } else { CP_WAIT0(); }
        __syncthreads();

        const float* pst = ps[buf];
        const int tbase = s * STG_T;
#pragma unroll 1
        for (int tl = 0; tl < STG_T; tl += 2) {
            {
                float hn = scan_step1(hs[0], w, pst[tl * HH + j]);
                hs[1][j] = hn;
                orow[(size_t)(tbase + tl) * HH] = hn;
                __syncthreads();
            }
            {
                float hn = scan_step1(hs[1], w, pst[(tl + 1) * HH + j]);
                hs[0][j] = hn;
                orow[(size_t)(tbase + tl + 1) * HH] = hn;
                __syncthreads();
            }
        }

        // refill stage s+2 into the buffer just consumed
        if (s + 2 < nst) {
            scan_prefetch(ps[buf], pre, (s + 2) * STG_T, j);
        }
        CP_COMMIT();
    }
}

// ---------------------------------------------------------------------------
extern "C" void kernel_launch(void* const* d_in, const int* in_sizes, int n_in,
                              void* d_out, int out_size)
{
    const float* x     = (const float*)d_in[0];
    const float* Wih0  = (const float*)d_in[1];
    const float* Whh0  = (const float*)d_in[2];
    const float* bih0  = (const float*)d_in[3];
    const float* bhh0  = (const float*)d_in[4];
    const float* Wih1  = (const float*)d_in[5];
    const float* Whh1  = (const float*)d_in[6];
    const float* bih1  = (const float*)d_in[7];
    const float* bhh1  = (const float*)d_in[8];
    float* out = (float*)d_out;

    // layer 0
    proj0_kernel<<<BB * TT / ROWS0, 128>>>(x, Wih0, bih0, bhh0);
    scan_kernel<<<BB, 128>>>(Whh0, nullptr);

    // layer 1
    proj1_kernel<<<PJ1_GRID, 128>>>(Wih1, bih1, bhh1);
    scan_kernel<<<BB, 128>>>(Whh1, out);
}

// round 15
// speedup vs baseline: 1.4622x; 1.1473x over previous
#include <cuda_runtime.h>
#include <cstdint>

#define BB 256
#define TT 1024
#define HH 128
#define II 19
#define STG_T 32   // timesteps per cp.async stage in scan

// proj1-mma geometry
#define AP   132                 // A smem row stride (floats)
#define WP   136                 // W smem row stride (bf16)
#define CHROWS 128               // A rows per chunk
#define NCH  (BB * TT / CHROWS)  // 2048 chunks
#define PJ1_GRID 148
#define PJ1_SMEM (2*CHROWS*AP*4 + 2*HH*WP*2 + HH*4)

// Scratch (device globals; no runtime allocation allowed)
__device__ float g_pre[BB * TT * HH];   // pre-activations for current layer
__device__ float g_out1[BB * TT * HH];  // layer-0 hidden outputs

typedef unsigned long long ull;
typedef unsigned int u32;

__device__ __forceinline__ ull ffma2(ull a, ull b, ull c) {
    ull d;
    asm("fma.rn.f32x2 %0, %1, %2, %3;" : "=l"(d) : "l"(a), "l"(b), "l"(c));
    return d;
}

__device__ __forceinline__ ull fadd2(ull a, ull b) {
    ull d;
    asm("add.rn.f32x2 %0, %1, %2;" : "=l"(d) : "l"(a), "l"(b));
    return d;
}

__device__ __forceinline__ float hsum2(ull a) {
    float x, y;
    asm("mov.b64 {%0, %1}, %2;" : "=f"(x), "=f"(y) : "l"(a));
    return x + y;
}

// single-MUFU tanh (validated R10: final rel_err 5.5e-6)
__device__ __forceinline__ float fast_tanh(float x) {
    float r;
    asm("tanh.approx.f32 %0, %1;" : "=f"(r) : "f"(x));
    return r;
}

__device__ __forceinline__ uint32_t s2u(const void* p) {
    return (uint32_t)__cvta_generic_to_shared(p);
}
#define CP_ASYNC16(dst, src) \
    asm volatile("cp.async.ca.shared.global [%0], [%1], 16;" :: "r"(dst), "l"(src))
#define CP_COMMIT() asm volatile("cp.async.commit_group;" ::: "memory")
#define CP_WAIT0()  asm volatile("cp.async.wait_group 0;" ::: "memory")
#define CP_WAIT1()  asm volatile("cp.async.wait_group 1;" ::: "memory")

// pack two fp32 into bf16x2: hi half = first arg, lo half = second arg
__device__ __forceinline__ u32 pack_bf16(float hi, float lo) {
    u32 d;
    asm("cvt.rn.bf16x2.f32 %0, %1, %2;" : "=r"(d) : "f"(hi), "f"(lo));
    return d;
}
__device__ __forceinline__ float bflo2f(u32 h) {  // lo-half bf16 -> f32
    return __uint_as_float(h << 16);
}
__device__ __forceinline__ float bfhi2f(u32 h) {  // hi-half bf16 -> f32
    return __uint_as_float(h & 0xFFFF0000u);
}

__device__ __forceinline__ void mma_bf16(float& c0, float& c1, float& c2, float& c3,
                                         u32 a0, u32 a1, u32 a2, u32 a3,
                                         u32 b0, u32 b1) {
    asm("mma.sync.aligned.m16n8k16.row.col.f32.bf16.bf16.f32 "
        "{%0,%1,%2,%3}, {%4,%5,%6,%7}, {%8,%9}, {%0,%1,%2,%3};"
        : "+f"(c0), "+f"(c1), "+f"(c2), "+f"(c3)
        : "r"(a0), "r"(a1), "r"(a2), "r"(a3), "r"(b0), "r"(b1));
}

// ---------------------------------------------------------------------------
// proj0: pre = x @ W_ih0^T + (b_ih0 + b_hh0).  x:[B,T,19], W:[128,19]
// ---------------------------------------------------------------------------
#define ROWS0 8
__global__ void __launch_bounds__(128) proj0_kernel(
    const float* __restrict__ x,
    const float* __restrict__ Wih,
    const float* __restrict__ bih,
    const float* __restrict__ bhh)
{
    __shared__ float xs[ROWS0 * II];
    const int j   = threadIdx.x;
    const int blk = blockIdx.x;

    float w[II];
#pragma unroll
    for (int i = 0; i < II; i++) w[i] = Wih[j * II + i];
    const float bias = bih[j] + bhh[j];

    const float* src = x + (size_t)blk * ROWS0 * II;
    for (int i = j; i < ROWS0 * II; i += 128) xs[i] = src[i];
    __syncthreads();

#pragma unroll
    for (int r = 0; r < ROWS0; r++) {
        float acc = bias;
#pragma unroll
        for (int i = 0; i < II; i++) acc += xs[r * II + i] * w[i];
        g_pre[((size_t)blk * ROWS0 + r) * HH + j] = acc;
    }
}

// ---------------------------------------------------------------------------
// proj1 via tensor cores: pre = out1 @ W_ih1^T + bias, bf16 split-3 MMA.
// 148 persistent CTAs x 256 threads (8 warps). W converted once per CTA to
// bf16 hi/lo in smem ([n][k] row-major, stride WP -> conflict-free B loads,
// B-frag k-pairs contiguous). A chunks of 128 rows cp.async double-buffered;
// warp w owns rows [16w,16w+16) of each chunk. A-frags built by direct
// LDS.64 + cvt (fragment layouts per PTX m16n8k16 spec). C = 4 regs/ntile.
// ---------------------------------------------------------------------------
__device__ __forceinline__ void pj1_prefetchA(float* Abuf, int chunk, int tid) {
    uint32_t dbase = s2u(Abuf);
    const float* src = g_out1 + (size_t)chunk * CHROWS * HH;
#pragma unroll
    for (int it = 0; it < CHROWS * (HH / 4) / 256; it++) {   // 16 iters
        int i   = it * 256 + tid;        // [0, 4096) 16B chunks
        int row = i >> 5;
        int c   = i & 31;
        CP_ASYNC16(dbase + (row * AP + c * 4) * 4, src + row * HH + c * 4);
    }
}

__global__ void __launch_bounds__(256, 1) proj1_mma_kernel(
    const float* __restrict__ Wih,
    const float* __restrict__ bih,
    const float* __restrict__ bhh)
{
    extern __shared__ __align__(16) float dyn[];
    float*          Ash = dyn;                                  // [2][CHROWS*AP]
    unsigned short* Whi = (unsigned short*)(dyn + 2 * CHROWS * AP);
    unsigned short* Wlo = Whi + HH * WP;
    float*          bsh = (float*)(Wlo + HH * WP);

    const int tid  = threadIdx.x;
    const int warp = tid >> 5;
    const int lane = tid & 31;
    const int g    = lane >> 2;      // fragment row/col group
    const int tq   = lane & 3;       // fragment quad index

    int chunk = blockIdx.x;
    if (chunk < NCH) pj1_prefetchA(Ash, chunk, tid);
    CP_COMMIT();

    // one-time W conversion: fp32 -> bf16 hi + lo residual (overlaps cp.async)
    if (tid < HH) {
        const int j = tid;
#pragma unroll 4
        for (int k4 = 0; k4 < HH / 4; k4++) {
            float4 v = *(const float4*)(Wih + j * HH + k4 * 4);
            u32 h0 = pack_bf16(v.y, v.x);
            u32 h1 = pack_bf16(v.w, v.z);
            float r0 = v.x - bflo2f(h0);
            float r1 = v.y - bfhi2f(h0);
            float r2 = v.z - bflo2f(h1);
            float r3 = v.w - bfhi2f(h1);
            u32 l0 = pack_bf16(r1, r0);
            u32 l1 = pack_bf16(r3, r2);
            *(u32*)&Whi[j * WP + k4 * 4]     = h0;
            *(u32*)&Whi[j * WP + k4 * 4 + 2] = h1;
            *(u32*)&Wlo[j * WP + k4 * 4]     = l0;
            *(u32*)&Wlo[j * WP + k4 * 4 + 2] = l1;
        }
        bsh[j] = bih[j] + bhh[j];
    }

    int buf = 0;
#pragma unroll 1
    while (chunk < NCH) {
        const int next = chunk + PJ1_GRID;
        CP_WAIT0();
        __syncthreads();               // A chunk + (first iter) W/b visible
        if (next < NCH) pj1_prefetchA(Ash + (buf ^ 1) * CHROWS * AP, next, tid);
        CP_COMMIT();

        const float* At = Ash + buf * CHROWS * AP;
        const int rbase = warp * 16;

        // A fragments for all 8 k-tiles, hi + lo split
        u32 ahi[8][4], alo[8][4];
#pragma unroll
        for (int kt = 0; kt < 8; kt++) {
            const float* p = At + (rbase + g) * AP + kt * 16 + 2 * tq;
            float2 x00 = *(const float2*)p;                 // row g,   k 2t..2t+1
            float2 x10 = *(const float2*)(p + 8 * AP);      // row g+8
            float2 x01 = *(const float2*)(p + 8);           // row g,   k +8
            float2 x11 = *(const float2*)(p + 8 * AP + 8);  // row g+8, k +8
            u32 h0 = pack_bf16(x00.y, x00.x);
            u32 h1 = pack_bf16(x10.y, x10.x);
            u32 h2 = pack_bf16(x01.y, x01.x);
            u32 h3 = pack_bf16(x11.y, x11.x);
            ahi[kt][0] = h0; ahi[kt][1] = h1; ahi[kt][2] = h2; ahi[kt][3] = h3;
            alo[kt][0] = pack_bf16(x00.y - bfhi2f(h0), x00.x - bflo2f(h0));
            alo[kt][1] = pack_bf16(x10.y - bfhi2f(h1), x10.x - bflo2f(h1));
            alo[kt][2] = pack_bf16(x01.y - bfhi2f(h2), x01.x - bflo2f(h2));
            alo[kt][3] = pack_bf16(x11.y - bfhi2f(h3), x11.x - bflo2f(h3));
        }

        const size_t rowg = (size_t)chunk * CHROWS + rbase;
#pragma unroll 1
        for (int n = 0; n < 16; n++) {
            float c0 = 0.f, c1 = 0.f, c2 = 0.f, c3 = 0.f;
            const unsigned short* whb = Whi + (n * 8 + g) * WP;
            const unsigned short* wlb = Wlo + (n * 8 + g) * WP;
#pragma unroll
            for (int kt = 0; kt < 8; kt++) {
                u32 bh0 = *(const u32*)(whb + kt * 16 + 2 * tq);
                u32 bh1 = *(const u32*)(whb + kt * 16 + 2 * tq + 8);
                u32 bl0 = *(const u32*)(wlb + kt * 16 + 2 * tq);
                u32 bl1 = *(const u32*)(wlb + kt * 16 + 2 * tq + 8);
                mma_bf16(c0, c1, c2, c3,
                         ahi[kt][0], ahi[kt][1], ahi[kt][2], ahi[kt][3], bh0, bh1);
                mma_bf16(c0, c1, c2, c3,
                         ahi[kt][0], ahi[kt][1], ahi[kt][2], ahi[kt][3], bl0, bl1);
                mma_bf16(c0, c1, c2, c3,
                         alo[kt][0], alo[kt][1], alo[kt][2], alo[kt][3], bh0, bh1);
            }
            float2 bb = *(const float2*)&bsh[n * 8 + 2 * tq];
            float2 s0 = make_float2(c0 + bb.x, c1 + bb.y);
            float2 s1 = make_float2(c2 + bb.x, c3 + bb.y);
            *(float2*)&g_pre[(rowg + g)     * HH + n * 8 + 2 * tq] = s0;
            *(float2*)&g_pre[(rowg + g + 8) * HH + n * 8 + 2 * tq] = s1;
        }
        chunk = next;
        buf ^= 1;
    }
}

// ---------------------------------------------------------------------------
// scan: h_t = tanh(pre_t + W_hh h_{t-1}).  ONE batch row per CTA, 256 CTAs,
// 2 CTAs/SM. W_hh row register-resident (64 packed regs), 4 accumulator
// chains. pre staged by cp.async in double-buffered 32-step stages.
// outp == nullptr -> write g_out1 (layer 0), else write outp (layer 1).
// ---------------------------------------------------------------------------
__device__ __forceinline__ void scan_prefetch(float* dst, const float* pre,
                                              int t0, int j) {
    uint32_t dbase = s2u(dst);
#pragma unroll
    for (int it = 0; it < STG_T * HH / 4 / 128; it++) {   // 8 iters
        int lin = it * 128 + j;                 // [0,1024) 16B chunks
        int tt  = lin >> 5;                     // timestep within stage
        int c   = lin & 31;                     // 16B chunk within row
        CP_ASYNC16(dbase + lin * 16, pre + (size_t)(t0 + tt) * HH + c * 4);
    }
}

__device__ __forceinline__ float scan_step1(const float* hp, const ull* w, float p) {
    const ulonglong2* h2 = (const ulonglong2*)hp;
    ull a0 = 0, a1 = 0, a2 = 0, a3 = 0;
#pragma unroll
    for (int q = 0; q < 16; q++) {
        ulonglong2 v = h2[2 * q];
        ulonglong2 u = h2[2 * q + 1];
        a0 = ffma2(v.x, w[4 * q],     a0);
        a1 = ffma2(v.y, w[4 * q + 1], a1);
        a2 = ffma2(u.x, w[4 * q + 2], a2);
        a3 = ffma2(u.y, w[4 * q + 3], a3);
    }
    ull s = fadd2(fadd2(a0, a1), fadd2(a2, a3));
    return fast_tanh(p + hsum2(s));
}

__global__ void __launch_bounds__(128, 2) scan_kernel(
    const float* __restrict__ Whh,
    float* __restrict__ outp)
{
    __shared__ __align__(16) float hs[2][HH];            // double-buffered h
    __shared__ __align__(16) float ps[2][STG_T * HH];    // staged pre
    const int j = threadIdx.x;
    const int b = blockIdx.x;

    const float* pre = g_pre + (size_t)b * TT * HH;

    scan_prefetch(ps[0], pre, 0, j);
    CP_COMMIT();
    scan_prefetch(ps[1], pre, STG_T, j);
    CP_COMMIT();

    ull w[64];
    {
        const ulonglong2* wr = (const ulonglong2*)(Whh + j * HH);
#pragma unroll
        for (int q = 0; q < 32; q++) {
            ulonglong2 t = wr[q];
            w[2 * q]     = t.x;
            w[2 * q + 1] = t.y;
        }
    }

    float* out  = outp ? outp : g_out1;
    float* orow = out + (size_t)b * TT * HH + j;

    hs[0][j] = 0.0f;
    __syncthreads();

    const int nst = TT / STG_T;
#pragma unroll 1
    for (int s = 0; s < nst; s++) {
        const int buf = s & 1;
        if (s + 1 < nst) { CP_WAIT1(); } else { CP_WAIT0(); }
        __syncthreads();

        const float* pst = ps[buf];
        const int tbase = s * STG_T;
#pragma unroll 1
        for (int tl = 0; tl < STG_T; tl += 2) {
            {
                float hn = scan_step1(hs[0], w, pst[tl * HH + j]);
                hs[1][j] = hn;
                orow[(size_t)(tbase + tl) * HH] = hn;
                __syncthreads();
            }
            {
                float hn = scan_step1(hs[1], w, pst[(tl + 1) * HH + j]);
                hs[0][j] = hn;
                orow[(size_t)(tbase + tl + 1) * HH] = hn;
                __syncthreads();
            }
        }

        if (s + 2 < nst) {
            scan_prefetch(ps[buf], pre, (s + 2) * STG_T, j);
        }
        CP_COMMIT();
    }
}

// ---------------------------------------------------------------------------
extern "C" void kernel_launch(void* const* d_in, const int* in_sizes, int n_in,
                              void* d_out, int out_size)
{
    const float* x     = (const float*)d_in[0];
    const float* Wih0  = (const float*)d_in[1];
    const float* Whh0  = (const float*)d_in[2];
    const float* bih0  = (const float*)d_in[3];
    const float* bhh0  = (const float*)d_in[4];
    const float* Wih1  = (const float*)d_in[5];
    const float* Whh1  = (const float*)d_in[6];
    const float* bih1  = (const float*)d_in[7];
    const float* bhh1  = (const float*)d_in[8];
    float* out = (float*)d_out;

    // opt-in dynamic smem for the mma kernel (idempotent, capture-safe)
    cudaFuncSetAttribute(proj1_mma_kernel,
                         cudaFuncAttributeMaxDynamicSharedMemorySize, PJ1_SMEM);

    // layer 0
    proj0_kernel<<<BB * TT / ROWS0, 128>>>(x, Wih0, bih0, bhh0);
    scan_kernel<<<BB, 128>>>(Whh0, nullptr);

    // layer 1
    proj1_mma_kernel<<<PJ1_GRID, 256, PJ1_SMEM>>>(Wih1, bih1, bhh1);
    scan_kernel<<<BB, 128>>>(Whh1, out);
}